// round 1
// baseline (speedup 1.0000x reference)
#include <cuda_runtime.h>
#include <math.h>

#define S_SPK 1024
#define U_UTT 64
#define E_DIM 256
#define SU (S_SPK * U_UTT)

#define TM 128
#define TN 128
#define BK 16

// Scratch (no allocations allowed in kernel_launch)
__device__ float g_Bn[S_SPK * E_DIM];   // normalized speaker-sum directions [S, E]
__device__ float g_diag[SU];            // per-utterance diagonal cosine
__device__ float g_acc[2];              // loss_sum, correct_sum

// ---------------------------------------------------------------------------
// Kernel 0: reset accumulators (determinism across graph replays)
// ---------------------------------------------------------------------------
__global__ void zero_acc_kernel() {
    g_acc[0] = 0.f;
    g_acc[1] = 0.f;
}

// ---------------------------------------------------------------------------
// Kernel 1: per-speaker sums, normalized centroid directions, diagonal cosines
//   sum_j[e]       = sum_u e[j,u,e]
//   Bn[j]          = sum_j / |sum_j|
//   diag[j,u]      = (e_ju . sum_j - |e_ju|^2) / sqrt(|sum_j|^2 - 2 e.sum + |e|^2)
// One block per speaker, 256 threads (one per E column).
// ---------------------------------------------------------------------------
__global__ void centroid_kernel(const float* __restrict__ emb) {
    int j = blockIdx.x;
    int t = threadIdx.x;                 // 0..255 == E column
    const float* base = emb + (size_t)j * U_UTT * E_DIM;

    float sum = 0.f;
#pragma unroll
    for (int u = 0; u < U_UTT; u++) sum += base[u * E_DIM + t];

    __shared__ float sum_sh[E_DIM];
    __shared__ float red[8];
    __shared__ float ssq_sh;
    sum_sh[t] = sum;

    // block-reduce |sum|^2
    float v = sum * sum;
#pragma unroll
    for (int o = 16; o > 0; o >>= 1) v += __shfl_xor_sync(0xffffffffu, v, o);
    if ((t & 31) == 0) red[t >> 5] = v;
    __syncthreads();
    if (t == 0) {
        float tot = 0.f;
#pragma unroll
        for (int i = 0; i < 8; i++) tot += red[i];
        ssq_sh = tot;
    }
    __syncthreads();
    float ssq = ssq_sh;

    // normalized centroid direction
    float inv = rsqrtf(ssq);
    g_Bn[(size_t)j * E_DIM + t] = sum_sh[t] * inv;

    // per-utterance diag: 8 warps x 8 utterances each
    int warp = t >> 5, lane = t & 31;
    for (int u = warp; u < U_UTT; u += 8) {
        const float* row = base + u * E_DIM;
        float d = 0.f, n2 = 0.f;
#pragma unroll
        for (int i = 0; i < 8; i++) {
            float x = row[lane + 32 * i];
            d  += x * sum_sh[lane + 32 * i];
            n2 += x * x;
        }
#pragma unroll
        for (int o = 16; o > 0; o >>= 1) {
            d  += __shfl_xor_sync(0xffffffffu, d,  o);
            n2 += __shfl_xor_sync(0xffffffffu, n2, o);
        }
        if (lane == 0) {
            float denom = ssq - 2.f * d + n2;
            g_diag[j * U_UTT + u] = (d - n2) * rsqrtf(denom);
        }
    }
}

// ---------------------------------------------------------------------------
// Kernel 2: fused GEMM + online softmax/argmax + loss/accuracy accumulation.
// Each block: TM=128 rows x all 1024 cols (8 col tiles of TN=128).
// 256 threads (16x16), 8x8 microtile. Per-thread online-softmax state over
// the 64 columns it owns; shuffle-combined across the 16 threads per row.
// ---------------------------------------------------------------------------
__global__ __launch_bounds__(256, 2)
void ge2e_main_kernel(const float* __restrict__ emb,
                      const float* __restrict__ wp,
                      const float* __restrict__ bp)
{
    __shared__ float As[BK][TM + 4];
    __shared__ float Bs[BK][TN + 4];

    int tid = threadIdx.x;
    int tx = tid & 15, ty = tid >> 4;
    int rowBase = blockIdx.x * TM;
    float w = wp[0], bb = bp[0];

    // per-row state: rows rowBase + ty*8 + i
    float m[8], s[8], bv[8], dg[8];
    int bi[8];
#pragma unroll
    for (int i = 0; i < 8; i++) {
        m[i] = -1e30f; s[i] = 0.f; bv[i] = -1e30f; bi[i] = 0;
        dg[i] = g_diag[rowBase + ty * 8 + i];
    }

    for (int ct = 0; ct < S_SPK / TN; ct++) {
        int colBase = ct * TN;
        float acc[8][8];
#pragma unroll
        for (int i = 0; i < 8; i++)
#pragma unroll
            for (int jj = 0; jj < 8; jj++) acc[i][jj] = 0.f;

        for (int kb = 0; kb < E_DIM / BK; kb++) {
            // load A tile [TM x BK] transposed into As[k][m]
#pragma unroll
            for (int q = 0; q < 2; q++) {
                int idx = tid * 2 + q;
                int r = idx >> 2, cv = idx & 3;
                float4 v = *(const float4*)(emb + (size_t)(rowBase + r) * E_DIM + kb * BK + cv * 4);
                As[cv * 4 + 0][r] = v.x;
                As[cv * 4 + 1][r] = v.y;
                As[cv * 4 + 2][r] = v.z;
                As[cv * 4 + 3][r] = v.w;
            }
            // load B tile [TN x BK] transposed into Bs[k][n]
#pragma unroll
            for (int q = 0; q < 2; q++) {
                int idx = tid * 2 + q;
                int n = idx >> 2, cv = idx & 3;
                float4 v = *(const float4*)(g_Bn + (size_t)(colBase + n) * E_DIM + kb * BK + cv * 4);
                Bs[cv * 4 + 0][n] = v.x;
                Bs[cv * 4 + 1][n] = v.y;
                Bs[cv * 4 + 2][n] = v.z;
                Bs[cv * 4 + 3][n] = v.w;
            }
            __syncthreads();
#pragma unroll
            for (int k = 0; k < BK; k++) {
                float a[8], bf[8];
#pragma unroll
                for (int i = 0; i < 8; i++) a[i] = As[k][ty * 8 + i];
#pragma unroll
                for (int jj = 0; jj < 8; jj++) bf[jj] = Bs[k][tx * 8 + jj];
#pragma unroll
                for (int i = 0; i < 8; i++)
#pragma unroll
                    for (int jj = 0; jj < 8; jj++)
                        acc[i][jj] = fmaf(a[i], bf[jj], acc[i][jj]);
            }
            __syncthreads();
        }

        // fold tile into online softmax / argmax
#pragma unroll
        for (int i = 0; i < 8; i++) {
            int rg = rowBase + ty * 8 + i;
            int spk = rg >> 6;
#pragma unroll
            for (int jj = 0; jj < 8; jj++) {
                int c = colBase + tx * 8 + jj;
                float l = (c == spk) ? fmaf(w, dg[i], bb) : fmaf(w, acc[i][jj], bb);
                if (l > bv[i]) { bv[i] = l; bi[i] = c; }   // strict >: first-max wins
                if (l > m[i]) {
                    s[i] = s[i] * __expf(m[i] - l) + 1.f;
                    m[i] = l;
                } else {
                    s[i] += __expf(l - m[i]);
                }
            }
        }
    }

    // combine across the 16 tx-threads sharing each row (xor within half-warps)
#pragma unroll
    for (int i = 0; i < 8; i++) {
        float mm = m[i], ss = s[i], bvv = bv[i];
        int bii = bi[i];
#pragma unroll
        for (int o = 1; o < 16; o <<= 1) {
            float om  = __shfl_xor_sync(0xffffffffu, mm,  o);
            float os  = __shfl_xor_sync(0xffffffffu, ss,  o);
            float obv = __shfl_xor_sync(0xffffffffu, bvv, o);
            int   obi = __shfl_xor_sync(0xffffffffu, bii, o);
            float nm = fmaxf(mm, om);
            ss = ss * __expf(mm - nm) + os * __expf(om - nm);
            mm = nm;
            if (obv > bvv || (obv == bvv && obi < bii)) { bvv = obv; bii = obi; }
        }
        m[i] = mm; s[i] = ss; bv[i] = bvv; bi[i] = bii;
    }

    // per-row loss + correctness (tx==0 holds the combined state)
    float lossLocal = 0.f, corrLocal = 0.f;
    if (tx == 0) {
#pragma unroll
        for (int i = 0; i < 8; i++) {
            int rg = rowBase + ty * 8 + i;
            int spk = rg >> 6;
            float lgt = fmaf(w, dg[i], bb);      // ground-truth logit = diagonal
            lossLocal += (m[i] + __logf(s[i])) - lgt;
            corrLocal += (bi[i] == spk) ? 1.f : 0.f;
        }
    }

    // block reduce -> one atomic pair per block
    __shared__ float redL[8], redC[8];
#pragma unroll
    for (int o = 16; o > 0; o >>= 1) {
        lossLocal += __shfl_xor_sync(0xffffffffu, lossLocal, o);
        corrLocal += __shfl_xor_sync(0xffffffffu, corrLocal, o);
    }
    if ((tid & 31) == 0) { redL[tid >> 5] = lossLocal; redC[tid >> 5] = corrLocal; }
    __syncthreads();
    if (tid == 0) {
        float L = 0.f, C = 0.f;
#pragma unroll
        for (int i = 0; i < 8; i++) { L += redL[i]; C += redC[i]; }
        atomicAdd(&g_acc[0], L);
        atomicAdd(&g_acc[1], C);
    }
}

// ---------------------------------------------------------------------------
// Kernel 3: finalize
// ---------------------------------------------------------------------------
__global__ void finalize_kernel(float* __restrict__ out) {
    out[0] = g_acc[0] * (1.f / (float)SU);   // mean loss
    out[1] = g_acc[1] * (1.f / (float)SU);   // accuracy
}

extern "C" void kernel_launch(void* const* d_in, const int* in_sizes, int n_in,
                              void* d_out, int out_size) {
    const float* emb = (const float*)d_in[0];
    const float* wp  = (const float*)d_in[1];
    const float* bp  = (const float*)d_in[2];
    float* out = (float*)d_out;

    zero_acc_kernel<<<1, 1>>>();
    centroid_kernel<<<S_SPK, 256>>>(emb);
    ge2e_main_kernel<<<SU / TM, 256>>>(emb, wp, bp);
    finalize_kernel<<<1, 1>>>(out);
}

// round 4
// speedup vs baseline: 2.0888x; 2.0888x over previous
#include <cuda_runtime.h>
#include <cuda_bf16.h>
#include <math.h>
#include <stdint.h>

#define S_SPK 1024
#define U_UTT 64
#define E_DIM 256
#define SU (S_SPK * U_UTT)
#define LOG2E 1.4426950408889634f
#define M2 2e-4f            // decision margin in log2-logit units (~70 sigma)
#define CAND_CAP (1 << 20)

// ---------------- scratch ----------------
__device__ __nv_bfloat16 g_Ah[(size_t)SU * E_DIM];
__device__ __nv_bfloat16 g_Al[(size_t)SU * E_DIM];
__device__ __nv_bfloat16 g_Bh[S_SPK * E_DIM];
__device__ __nv_bfloat16 g_Bl[S_SPK * E_DIM];
__device__ float g_Bn[S_SPK * E_DIM];      // fp32 normalized centroids (stage 2)
__device__ float g_diag[SU];
__device__ float g_acc[2];
__device__ unsigned int g_ncand;
__device__ unsigned int g_cand[CAND_CAP];  // (row<<10)|col
__device__ unsigned int g_und[SU / 32];
__device__ unsigned int g_beaten[SU / 32];

// ---------------- helpers ----------------
__device__ __forceinline__ uint32_t smem_u32(const void* p) {
    uint32_t a;
    asm("{ .reg .u64 t; cvta.to.shared.u64 t, %1; cvt.u32.u64 %0, t; }" : "=r"(a) : "l"(p));
    return a;
}
__device__ __forceinline__ void cp16(uint32_t dst, const void* src) {
    asm volatile("cp.async.cg.shared.global [%0], [%1], 16;" :: "r"(dst), "l"(src));
}
#define CP_COMMIT() asm volatile("cp.async.commit_group;" ::: "memory")
#define CP_WAIT2()  asm volatile("cp.async.wait_group 2;" ::: "memory")

__device__ __forceinline__ void ldsm4(uint32_t* r, uint32_t addr) {
    asm volatile("ldmatrix.sync.aligned.m8n8.x4.shared.b16 {%0,%1,%2,%3}, [%4];"
                 : "=r"(r[0]), "=r"(r[1]), "=r"(r[2]), "=r"(r[3]) : "r"(addr));
}
__device__ __forceinline__ void mma16816(float* c, const uint32_t* a, uint32_t b0, uint32_t b1) {
    asm volatile("mma.sync.aligned.m16n8k16.row.col.f32.bf16.bf16.f32 "
                 "{%0,%1,%2,%3}, {%4,%5,%6,%7}, {%8,%9}, {%0,%1,%2,%3};"
                 : "+f"(c[0]), "+f"(c[1]), "+f"(c[2]), "+f"(c[3])
                 : "r"(a[0]), "r"(a[1]), "r"(a[2]), "r"(a[3]), "r"(b0), "r"(b1));
}

// ---------------------------------------------------------------------------
__global__ void zero_kernel() {
    int t = threadIdx.x;
    if (t == 0) { g_acc[0] = 0.f; g_acc[1] = 0.f; g_ncand = 0; }
    for (int w = t; w < SU / 32; w += 256) { g_und[w] = 0; g_beaten[w] = 0; }
}

// ---------------------------------------------------------------------------
// Kernel 1: speaker sums -> normalized dirs (fp32 + bf16 hi/lo), diag cosines,
//           embed bf16 hi/lo split.
// ---------------------------------------------------------------------------
__global__ void centroid_kernel(const float* __restrict__ emb) {
    int j = blockIdx.x;
    int t = threadIdx.x;  // E column
    const float* base = emb + (size_t)j * U_UTT * E_DIM;

    float sum = 0.f;
#pragma unroll
    for (int u = 0; u < U_UTT; u++) {
        float x = base[u * E_DIM + t];
        sum += x;
        __nv_bfloat16 h = __float2bfloat16_rn(x);
        g_Ah[((size_t)j * U_UTT + u) * E_DIM + t] = h;
        g_Al[((size_t)j * U_UTT + u) * E_DIM + t] = __float2bfloat16_rn(x - __bfloat162float(h));
    }

    __shared__ float sum_sh[E_DIM];
    __shared__ float red[8];
    __shared__ float ssq_sh;
    sum_sh[t] = sum;

    float v = sum * sum;
#pragma unroll
    for (int o = 16; o > 0; o >>= 1) v += __shfl_xor_sync(0xffffffffu, v, o);
    if ((t & 31) == 0) red[t >> 5] = v;
    __syncthreads();
    if (t == 0) {
        float tot = 0.f;
#pragma unroll
        for (int i = 0; i < 8; i++) tot += red[i];
        ssq_sh = tot;
    }
    __syncthreads();
    float ssq = ssq_sh;
    float bn = sum_sh[t] * rsqrtf(ssq);
    g_Bn[(size_t)j * E_DIM + t] = bn;
    __nv_bfloat16 bh = __float2bfloat16_rn(bn);
    g_Bh[(size_t)j * E_DIM + t] = bh;
    g_Bl[(size_t)j * E_DIM + t] = __float2bfloat16_rn(bn - __bfloat162float(bh));

    int warp = t >> 5, lane = t & 31;
    for (int u = warp; u < U_UTT; u += 8) {
        const float* row = base + u * E_DIM;
        float d = 0.f, n2 = 0.f;
#pragma unroll
        for (int i = 0; i < 8; i++) {
            float x = row[lane + 32 * i];
            d  += x * sum_sh[lane + 32 * i];
            n2 += x * x;
        }
#pragma unroll
        for (int o = 16; o > 0; o >>= 1) {
            d  += __shfl_xor_sync(0xffffffffu, d,  o);
            n2 += __shfl_xor_sync(0xffffffffu, n2, o);
        }
        if (lane == 0) {
            float denom = ssq - 2.f * d + n2;
            g_diag[j * U_UTT + u] = (d - n2) * rsqrtf(denom);
        }
    }
}

// ---------------------------------------------------------------------------
// Main kernel: bf16x2 GEMM (hi*hi + hi*lo + lo*hi -> ~fp32 precision),
// 128 rows x 1024 cols, K=256, fused softmax-sum / margin decisions.
// SMEM: A_hi 64K | A_lo 64K | B ring 3x32K (chunk = 128 cols x 64K hi+lo) | red 1K
// ---------------------------------------------------------------------------
#define AH_OFF 0
#define AL_OFF 65536
#define BB_OFF 131072
#define RED_OFF (BB_OFF + 3 * 32768)
#define SMEM_TOTAL (RED_OFF + 1024)

__global__ __launch_bounds__(256, 1)
void ge2e_main_kernel(const float* __restrict__ wp, const float* __restrict__ bp)
{
    extern __shared__ char smem[];
    const uint32_t sb = smem_u32(smem);
    const int tid = threadIdx.x;
    const int lane = tid & 31, wid = tid >> 5;
    const int wr = wid >> 1;          // row-group 0..3
    const int cg = wid & 1;           // col-group 0..1 (64 cols of the 128-col tile)
    const int rowBase = blockIdx.x * 128;

    const float wS = wp[0], bS = bp[0];
    const float w2 = wS * LOG2E, b2 = (bS - 5.f) * LOG2E;

    // ---- prologue: A hi+lo + B chunk 0 (group 0), chunks 1,2 (groups 1,2) ----
#pragma unroll
    for (int k = 0; k < 16; k++) {
        int i = tid + k * 256;
        int row = i >> 5, c = i & 31;
        uint32_t soff = row * 512 + ((c ^ (row & 7)) << 4);
        cp16(sb + AH_OFF + soff, g_Ah + (size_t)(rowBase + row) * E_DIM + c * 8);
        cp16(sb + AL_OFF + soff, g_Al + (size_t)(rowBase + row) * E_DIM + c * 8);
    }
#pragma unroll
    for (int g0 = 0; g0 < 3; g0++) {
#pragma unroll
        for (int half = 0; half < 2; half++) {
#pragma unroll
            for (int it = 0; it < 4; it++) {
                int idx = tid + it * 256;
                int row = idx >> 3, c = idx & 7;
                const __nv_bfloat16* src = (half ? g_Bl : g_Bh) +
                    (size_t)row * E_DIM + g0 * 64 + c * 8;   // tile 0, k64 = g0
                cp16(sb + BB_OFF + g0 * 32768 + half * 16384 + row * 128 +
                         ((c ^ (row & 7)) << 4), src);
            }
        }
        CP_COMMIT();
    }

    // ---- per-thread row state ----
    float sum[4] = {0.f, 0.f, 0.f, 0.f};
    float bv[4], t2d[4], gl[4];
    int spk[4], rloc[4];
#pragma unroll
    for (int mt = 0; mt < 2; mt++)
#pragma unroll
        for (int rb = 0; rb < 2; rb++) {
            int si = mt * 2 + rb;
            int r = wr * 32 + mt * 16 + rb * 8 + (lane >> 2);
            rloc[si] = r;
            int rg = rowBase + r;
            spk[si] = rg >> 6;
            float dg = g_diag[rg];
            t2d[si] = fmaf(w2, dg, b2);
            gl[si]  = fmaf(wS, dg, bS);
            bv[si] = -1e30f;
        }

    const int sA = lane & 7;
    const int hA = lane >> 4;
    const uint32_t aRow0h = sb + AH_OFF + (uint32_t)(wr * 32 + (lane & 15)) * 512;
    const uint32_t aRow0l = sb + AL_OFF + (uint32_t)(wr * 32 + (lane & 15)) * 512;
    const int bRow = cg * 64 + (lane & 7) + ((lane >> 4) & 1) * 8;
    const int hB = (lane >> 3) & 1;

    float c_[2][8][4];

    for (int g = 0; g < 32; g++) {               // chunk stream: tile = g>>2, k64 = g&3
        if ((g & 3) == 0) {
#pragma unroll
            for (int mt = 0; mt < 2; mt++)
#pragma unroll
                for (int nt = 0; nt < 8; nt++)
#pragma unroll
                    for (int q = 0; q < 4; q++) c_[mt][nt][q] = 0.f;
        }

        CP_WAIT2();
        __syncthreads();
        const uint32_t Bb = sb + BB_OFF + (uint32_t)(g % 3) * 32768;

#pragma unroll
        for (int kc = 0; kc < 4; kc++) {
            const int kg = (g & 3) * 4 + kc;     // global k16 index for A
            uint32_t ah[2][4], al[2][4];
#pragma unroll
            for (int mt = 0; mt < 2; mt++) {
                uint32_t aoff = (uint32_t)(mt * 16) * 512 +
                                (uint32_t)(((2 * kg + hA) ^ sA) << 4);
                ldsm4(ah[mt], aRow0h + aoff);
                ldsm4(al[mt], aRow0l + aoff);
            }
            uint32_t bh[4][4], bl[4][4];
#pragma unroll
            for (int np = 0; np < 4; np++) {
                uint32_t boff = (uint32_t)(bRow + np * 16) * 128 +
                                (uint32_t)(((2 * kc + hB) ^ sA) << 4);
                ldsm4(bh[np], Bb + boff);
                ldsm4(bl[np], Bb + 16384 + boff);
            }
#pragma unroll
            for (int mt = 0; mt < 2; mt++)
#pragma unroll
                for (int nt = 0; nt < 8; nt++) {
                    uint32_t bh0 = bh[nt >> 1][(nt & 1) * 2], bh1 = bh[nt >> 1][(nt & 1) * 2 + 1];
                    uint32_t bl0 = bl[nt >> 1][(nt & 1) * 2], bl1 = bl[nt >> 1][(nt & 1) * 2 + 1];
                    mma16816(c_[mt][nt], ah[mt], bh0, bh1);
                    mma16816(c_[mt][nt], al[mt], bh0, bh1);
                    mma16816(c_[mt][nt], ah[mt], bl0, bl1);
                }
        }
        __syncthreads();                          // slot free before overwrite

        if (g + 3 < 32) {
            int gn = g + 3;
            int tileN = gn >> 2, k64 = gn & 3, slot = gn % 3;
#pragma unroll
            for (int half = 0; half < 2; half++) {
#pragma unroll
                for (int it = 0; it < 4; it++) {
                    int idx = tid + it * 256;
                    int row = idx >> 3, c = idx & 7;
                    const __nv_bfloat16* src = (half ? g_Bl : g_Bh) +
                        (size_t)(tileN * 128 + row) * E_DIM + k64 * 64 + c * 8;
                    cp16(sb + BB_OFF + slot * 32768 + half * 16384 + row * 128 +
                             ((c ^ (row & 7)) << 4), src);
                }
            }
        }
        CP_COMMIT();

        if ((g & 3) == 3) {
            const int ct = g >> 2;
            // ---- fold tile into softmax/margin state ----
#pragma unroll
            for (int mt = 0; mt < 2; mt++)
#pragma unroll
                for (int nt = 0; nt < 8; nt++) {
                    int c0 = ct * 128 + cg * 64 + nt * 8 + 2 * (lane & 3);
#pragma unroll
                    for (int rb = 0; rb < 2; rb++) {
                        int si = mt * 2 + rb;
#pragma unroll
                        for (int q = 0; q < 2; q++) {
                            int cc = c0 + q;
                            float raw = fmaf(w2, c_[mt][nt][rb * 2 + q], b2);
                            float ls;
                            if (cc == spk[si]) {
                                ls = t2d[si];
                            } else {
                                ls = raw;
                                if (raw > bv[si]) bv[si] = raw;
                                if (fabsf(raw - t2d[si]) < M2) {
                                    unsigned int idx = atomicAdd(&g_ncand, 1u);
                                    if (idx < CAND_CAP)
                                        g_cand[idx] = ((unsigned)(rowBase + rloc[si]) << 10) | (unsigned)cc;
                                }
                            }
                            float e;
                            asm("ex2.approx.ftz.f32 %0, %1;" : "=f"(e) : "f"(ls));
                            sum[si] += e;
                        }
                    }
                }
        }
    }

    // ---- quad reduce ----
#pragma unroll
    for (int si = 0; si < 4; si++) {
#pragma unroll
        for (int o = 1; o < 4; o <<= 1) {
            sum[si] += __shfl_xor_sync(0xffffffffu, sum[si], o);
            float obv = __shfl_xor_sync(0xffffffffu, bv[si], o);
            if (obv > bv[si]) bv[si] = obv;
        }
    }

    // ---- cross col-group combine ----
    float* s_sum = (float*)(smem + RED_OFF);
    float* s_bv  = (float*)(smem + RED_OFF + 512);
    __syncthreads();
    if (cg == 1 && (lane & 3) == 0) {
#pragma unroll
        for (int si = 0; si < 4; si++) { s_sum[rloc[si]] = sum[si]; s_bv[rloc[si]] = bv[si]; }
    }
    __syncthreads();
    float lossLocal = 0.f, corrLocal = 0.f;
    if (cg == 0 && (lane & 3) == 0) {
#pragma unroll
        for (int si = 0; si < 4; si++) {
            float tot = sum[si] + s_sum[rloc[si]];
            float bvv = fmaxf(bv[si], s_bv[rloc[si]]);
            lossLocal += __logf(tot) + 5.f - gl[si];
            if (bvv < t2d[si] - M2) {
                corrLocal += 1.f;                         // definitely correct
            } else if (bvv < t2d[si] + M2) {              // undecided -> stage 2
                int rg = rowBase + rloc[si];
                atomicOr(&g_und[rg >> 5], 1u << (rg & 31));
            }                                             // else definitely incorrect
        }
    }
#pragma unroll
    for (int o = 4; o < 32; o <<= 1) {
        lossLocal += __shfl_xor_sync(0xffffffffu, lossLocal, o);
        corrLocal += __shfl_xor_sync(0xffffffffu, corrLocal, o);
    }
    if (cg == 0 && lane == 0) {
        atomicAdd(&g_acc[0], lossLocal);
        atomicAdd(&g_acc[1], corrLocal);
    }
}

// ---------------------------------------------------------------------------
// Stage 2: exact fp32 recheck of candidate (row,col) pairs; one warp per pair.
// ---------------------------------------------------------------------------
__global__ void recheck_kernel(const float* __restrict__ emb,
                               const float* __restrict__ wp,
                               const float* __restrict__ bp)
{
    unsigned int n = g_ncand;
    if (n > CAND_CAP) n = CAND_CAP;
    const float wS = wp[0], bS = bp[0];
    int lane = threadIdx.x & 31;
    int warpG = (blockIdx.x * blockDim.x + threadIdx.x) >> 5;
    int nW = (gridDim.x * blockDim.x) >> 5;
    for (unsigned int i = warpG; i < n; i += nW) {
        unsigned int pc = g_cand[i];
        int r = pc >> 10, c = pc & 1023;
        const float* e  = emb + (size_t)r * E_DIM;
        const float* bn = g_Bn + (size_t)c * E_DIM;
        float d = 0.f;
#pragma unroll
        for (int k = 0; k < 8; k++) d += e[lane + 32 * k] * bn[lane + 32 * k];
#pragma unroll
        for (int o = 16; o > 0; o >>= 1) d += __shfl_xor_sync(0xffffffffu, d, o);
        if (lane == 0) {
            float loff = fmaf(wS, d, bS);
            float ld   = fmaf(wS, g_diag[r], bS);
            int spk = r >> 6;
            bool beat = (loff > ld) || (loff == ld && c < spk);
            if (beat) atomicOr(&g_beaten[r >> 5], 1u << (r & 31));
        }
    }
}

// ---------------------------------------------------------------------------
__global__ void finalize_kernel(float* __restrict__ out) {
    __shared__ float red[8];
    int t = threadIdx.x;
    float cnt = 0.f;
    for (int w = t; w < SU / 32; w += 256)
        cnt += (float)__popc(g_und[w] & ~g_beaten[w]);
#pragma unroll
    for (int o = 16; o > 0; o >>= 1) cnt += __shfl_xor_sync(0xffffffffu, cnt, o);
    if ((t & 31) == 0) red[t >> 5] = cnt;
    __syncthreads();
    if (t == 0) {
        float tot = 0.f;
#pragma unroll
        for (int i = 0; i < 8; i++) tot += red[i];
        out[0] = g_acc[0] * (1.f / (float)SU);
        out[1] = (g_acc[1] + tot) * (1.f / (float)SU);
    }
}

extern "C" void kernel_launch(void* const* d_in, const int* in_sizes, int n_in,
                              void* d_out, int out_size) {
    const float* emb = (const float*)d_in[0];
    const float* wp  = (const float*)d_in[1];
    const float* bp  = (const float*)d_in[2];
    float* out = (float*)d_out;

    cudaFuncSetAttribute(ge2e_main_kernel,
                         cudaFuncAttributeMaxDynamicSharedMemorySize, SMEM_TOTAL);

    zero_kernel<<<1, 256>>>();
    centroid_kernel<<<S_SPK, 256>>>(emb);
    ge2e_main_kernel<<<SU / 128, 256, SMEM_TOTAL>>>(wp, bp);
    recheck_kernel<<<96, 256>>>(emb, wp, bp);
    finalize_kernel<<<1, 256>>>(out);
}

// round 5
// speedup vs baseline: 2.4119x; 1.1547x over previous
#include <cuda_runtime.h>
#include <cuda_bf16.h>
#include <math.h>
#include <stdint.h>

#define S_SPK 1024
#define U_UTT 64
#define E_DIM 256
#define SU (S_SPK * U_UTT)
#define LOG2E 1.4426950408889634f
#define LN2 0.6931471805599453f
#define M2 1e-4f            // decision margin in log2-logit units (~14 sigma)
#define CAND_CAP (1 << 20)

// ---------------- scratch ----------------
__device__ __nv_bfloat16 g_Ah[(size_t)SU * E_DIM];
__device__ __nv_bfloat16 g_Al[(size_t)SU * E_DIM];
__device__ __nv_bfloat16 g_Bh[S_SPK * E_DIM];
__device__ __nv_bfloat16 g_Bl[S_SPK * E_DIM];
__device__ float g_Bn[S_SPK * E_DIM];      // fp32 normalized centroids (stage 2)
__device__ float g_diag[SU];
__device__ float g_acc[2];
__device__ unsigned int g_ncand;
__device__ unsigned int g_cand[CAND_CAP];  // (row<<10)|col
__device__ unsigned int g_und[SU / 32];
__device__ unsigned int g_beaten[SU / 32];

// ---------------- helpers ----------------
__device__ __forceinline__ uint32_t smem_u32(const void* p) {
    uint32_t a;
    asm("{ .reg .u64 t; cvta.to.shared.u64 t, %1; cvt.u32.u64 %0, t; }" : "=r"(a) : "l"(p));
    return a;
}
__device__ __forceinline__ void cp16(uint32_t dst, const void* src) {
    asm volatile("cp.async.cg.shared.global [%0], [%1], 16;" :: "r"(dst), "l"(src));
}
#define CP_COMMIT() asm volatile("cp.async.commit_group;" ::: "memory")
#define CP_WAIT2()  asm volatile("cp.async.wait_group 2;" ::: "memory")

__device__ __forceinline__ void ldsm4(uint32_t* r, uint32_t addr) {
    asm volatile("ldmatrix.sync.aligned.m8n8.x4.shared.b16 {%0,%1,%2,%3}, [%4];"
                 : "=r"(r[0]), "=r"(r[1]), "=r"(r[2]), "=r"(r[3]) : "r"(addr));
}
__device__ __forceinline__ void mma16816(float* c, const uint32_t* a, uint32_t b0, uint32_t b1) {
    asm volatile("mma.sync.aligned.m16n8k16.row.col.f32.bf16.bf16.f32 "
                 "{%0,%1,%2,%3}, {%4,%5,%6,%7}, {%8,%9}, {%0,%1,%2,%3};"
                 : "+f"(c[0]), "+f"(c[1]), "+f"(c[2]), "+f"(c[3])
                 : "r"(a[0]), "r"(a[1]), "r"(a[2]), "r"(a[3]), "r"(b0), "r"(b1));
}

// ---------------------------------------------------------------------------
__global__ void zero_kernel() {
    int t = threadIdx.x;
    if (t == 0) { g_acc[0] = 0.f; g_acc[1] = 0.f; g_ncand = 0; }
    for (int w = t; w < SU / 32; w += 256) { g_und[w] = 0; g_beaten[w] = 0; }
}

// ---------------------------------------------------------------------------
// Kernel 1: speaker sums -> normalized dirs (fp32 + bf16 hi/lo), diag cosines,
//           embed bf16 hi/lo split.
// ---------------------------------------------------------------------------
__global__ void centroid_kernel(const float* __restrict__ emb) {
    int j = blockIdx.x;
    int t = threadIdx.x;  // E column
    const float* base = emb + (size_t)j * U_UTT * E_DIM;

    float sum = 0.f;
#pragma unroll
    for (int u = 0; u < U_UTT; u++) {
        float x = base[u * E_DIM + t];
        sum += x;
        __nv_bfloat16 h = __float2bfloat16_rn(x);
        g_Ah[((size_t)j * U_UTT + u) * E_DIM + t] = h;
        g_Al[((size_t)j * U_UTT + u) * E_DIM + t] = __float2bfloat16_rn(x - __bfloat162float(h));
    }

    __shared__ float sum_sh[E_DIM];
    __shared__ float red[8];
    __shared__ float ssq_sh;
    sum_sh[t] = sum;

    float v = sum * sum;
#pragma unroll
    for (int o = 16; o > 0; o >>= 1) v += __shfl_xor_sync(0xffffffffu, v, o);
    if ((t & 31) == 0) red[t >> 5] = v;
    __syncthreads();
    if (t == 0) {
        float tot = 0.f;
#pragma unroll
        for (int i = 0; i < 8; i++) tot += red[i];
        ssq_sh = tot;
    }
    __syncthreads();
    float ssq = ssq_sh;
    float bn = sum_sh[t] * rsqrtf(ssq);
    g_Bn[(size_t)j * E_DIM + t] = bn;
    __nv_bfloat16 bh = __float2bfloat16_rn(bn);
    g_Bh[(size_t)j * E_DIM + t] = bh;
    g_Bl[(size_t)j * E_DIM + t] = __float2bfloat16_rn(bn - __bfloat162float(bh));

    int warp = t >> 5, lane = t & 31;
    for (int u = warp; u < U_UTT; u += 8) {
        const float* row = base + u * E_DIM;
        float d = 0.f, n2 = 0.f;
#pragma unroll
        for (int i = 0; i < 8; i++) {
            float x = row[lane + 32 * i];
            d  += x * sum_sh[lane + 32 * i];
            n2 += x * x;
        }
#pragma unroll
        for (int o = 16; o > 0; o >>= 1) {
            d  += __shfl_xor_sync(0xffffffffu, d,  o);
            n2 += __shfl_xor_sync(0xffffffffu, n2, o);
        }
        if (lane == 0) {
            float denom = ssq - 2.f * d + n2;
            g_diag[j * U_UTT + u] = (d - n2) * rsqrtf(denom);
        }
    }
}

// ---------------------------------------------------------------------------
// Main kernel: bf16x2 GEMM (hi*hi + hi*lo + lo*hi), 128 rows x 1024 cols,
// K=256, fused softmax-sum / margin decisions. Epilogue of tile t is folded
// one quarter per chunk DURING tile t+1's MMA chunks (overlaps MUFU w/ tensor).
// SMEM: A_hi 64K | A_lo 64K | B ring 3x32K | red 1K
// ---------------------------------------------------------------------------
#define AH_OFF 0
#define AL_OFF 65536
#define BB_OFF 131072
#define RED_OFF (BB_OFF + 3 * 32768)
#define SMEM_TOTAL (RED_OFF + 1024)

__global__ __launch_bounds__(256, 1)
void ge2e_main_kernel(const float* __restrict__ wp, const float* __restrict__ bp)
{
    extern __shared__ char smem[];
    const uint32_t sb = smem_u32(smem);
    const int tid = threadIdx.x;
    const int lane = tid & 31, wid = tid >> 5;
    const int wr = wid >> 1;          // row-group 0..3
    const int cg = wid & 1;           // col-group 0..1
    const int rowBase = blockIdx.x * 128;

    const float wS = wp[0], bS = bp[0];
    const float w2 = wS * LOG2E, b2 = (bS - 5.f) * LOG2E;

    // ---- prologue: A hi+lo + B chunks 0..2 ----
#pragma unroll
    for (int k = 0; k < 16; k++) {
        int i = tid + k * 256;
        int row = i >> 5, c = i & 31;
        uint32_t soff = row * 512 + ((c ^ (row & 7)) << 4);
        cp16(sb + AH_OFF + soff, g_Ah + (size_t)(rowBase + row) * E_DIM + c * 8);
        cp16(sb + AL_OFF + soff, g_Al + (size_t)(rowBase + row) * E_DIM + c * 8);
    }
#pragma unroll
    for (int g0 = 0; g0 < 3; g0++) {
#pragma unroll
        for (int half = 0; half < 2; half++) {
#pragma unroll
            for (int it = 0; it < 4; it++) {
                int idx = tid + it * 256;
                int row = idx >> 3, c = idx & 7;
                const __nv_bfloat16* src = (half ? g_Bl : g_Bh) +
                    (size_t)row * E_DIM + g0 * 64 + c * 8;
                cp16(sb + BB_OFF + g0 * 32768 + half * 16384 + row * 128 +
                         ((c ^ (row & 7)) << 4), src);
            }
        }
        CP_COMMIT();
    }

    // ---- per-thread row state ----
    float sum[4] = {0.f, 0.f, 0.f, 0.f};
    float bv[4], t2d[4];
    int spk[4], rloc[4];
#pragma unroll
    for (int mt = 0; mt < 2; mt++)
#pragma unroll
        for (int rb = 0; rb < 2; rb++) {
            int si = mt * 2 + rb;
            int r = wr * 32 + mt * 16 + rb * 8 + (lane >> 2);
            rloc[si] = r;
            int rg = rowBase + r;
            spk[si] = rg >> 6;
            t2d[si] = fmaf(w2, g_diag[rg], b2);
            bv[si] = -1e30f;
        }

    const int sA = lane & 7;
    const int hA = lane >> 4;
    const uint32_t aRow0h = sb + AH_OFF + (uint32_t)(wr * 32 + (lane & 15)) * 512;
    const uint32_t aRow0l = sb + AL_OFF + (uint32_t)(wr * 32 + (lane & 15)) * 512;
    const int bRow = cg * 64 + (lane & 7) + ((lane >> 4) & 1) * 8;
    const int hB = (lane >> 3) & 1;

    float c_[2][8][4];    // current tile accumulators
    float cp_[2][8][4];   // previous tile accumulators (being folded)
    int prevTile = -1;

    // fold one (mt x 2-nt) quarter of the previous tile into softmax state
    auto fold2 = [&](int ct, int nt) {
#pragma unroll
        for (int mt = 0; mt < 2; mt++) {
            int c0 = ct * 128 + cg * 64 + nt * 8 + 2 * (lane & 3);
#pragma unroll
            for (int rb = 0; rb < 2; rb++) {
                int si = mt * 2 + rb;
#pragma unroll
                for (int q = 0; q < 2; q++) {
                    int cc = c0 + q;
                    float raw = fmaf(w2, cp_[mt][nt][rb * 2 + q], b2);
                    float ls;
                    if (cc == spk[si]) {
                        ls = t2d[si];
                    } else {
                        ls = raw;
                        if (raw > bv[si]) bv[si] = raw;
                        if (fabsf(raw - t2d[si]) < M2) {
                            unsigned int idx = atomicAdd(&g_ncand, 1u);
                            if (idx < CAND_CAP)
                                g_cand[idx] = ((unsigned)(rowBase + rloc[si]) << 10) | (unsigned)cc;
                        }
                    }
                    float e;
                    asm("ex2.approx.ftz.f32 %0, %1;" : "=f"(e) : "f"(ls));
                    sum[si] += e;
                }
            }
        }
    };

    for (int g = 0; g < 32; g++) {               // chunk: tile = g>>2, k64 = g&3
        if ((g & 3) == 0) {
#pragma unroll
            for (int mt = 0; mt < 2; mt++)
#pragma unroll
                for (int nt = 0; nt < 8; nt++)
#pragma unroll
                    for (int q = 0; q < 4; q++) c_[mt][nt][q] = 0.f;
        }

        CP_WAIT2();
        __syncthreads();
        const uint32_t Bb = sb + BB_OFF + (uint32_t)(g % 3) * 32768;

#pragma unroll
        for (int kc = 0; kc < 4; kc++) {
            const int kg = (g & 3) * 4 + kc;
            uint32_t ah[2][4], al[2][4];
#pragma unroll
            for (int mt = 0; mt < 2; mt++) {
                uint32_t aoff = (uint32_t)(mt * 16) * 512 +
                                (uint32_t)(((2 * kg + hA) ^ sA) << 4);
                ldsm4(ah[mt], aRow0h + aoff);
                ldsm4(al[mt], aRow0l + aoff);
            }
            uint32_t bh[4][4], bl[4][4];
#pragma unroll
            for (int np = 0; np < 4; np++) {
                uint32_t boff = (uint32_t)(bRow + np * 16) * 128 +
                                (uint32_t)(((2 * kc + hB) ^ sA) << 4);
                ldsm4(bh[np], Bb + boff);
                ldsm4(bl[np], Bb + 16384 + boff);
            }
#pragma unroll
            for (int mt = 0; mt < 2; mt++)
#pragma unroll
                for (int nt = 0; nt < 8; nt++) {
                    uint32_t bh0 = bh[nt >> 1][(nt & 1) * 2], bh1 = bh[nt >> 1][(nt & 1) * 2 + 1];
                    uint32_t bl0 = bl[nt >> 1][(nt & 1) * 2], bl1 = bl[nt >> 1][(nt & 1) * 2 + 1];
                    mma16816(c_[mt][nt], ah[mt], bh0, bh1);
                    mma16816(c_[mt][nt], al[mt], bh0, bh1);
                    mma16816(c_[mt][nt], ah[mt], bl0, bl1);
                }
        }
        __syncthreads();                          // slot free before overwrite

        if (g + 3 < 32) {
            int gn = g + 3;
            int tileN = gn >> 2, k64 = gn & 3, slot = gn % 3;
#pragma unroll
            for (int half = 0; half < 2; half++) {
#pragma unroll
                for (int it = 0; it < 4; it++) {
                    int idx = tid + it * 256;
                    int row = idx >> 3, c = idx & 7;
                    const __nv_bfloat16* src = (half ? g_Bl : g_Bh) +
                        (size_t)(tileN * 128 + row) * E_DIM + k64 * 64 + c * 8;
                    cp16(sb + BB_OFF + slot * 32768 + half * 16384 + row * 128 +
                             ((c ^ (row & 7)) << 4), src);
                }
            }
        }
        CP_COMMIT();

        // ---- staggered fold: quarter (g&3) of previous tile ----
        if (prevTile >= 0) {
            int p = g & 3;
            fold2(prevTile, 2 * p);
            fold2(prevTile, 2 * p + 1);
        }
        if ((g & 3) == 3) {
#pragma unroll
            for (int mt = 0; mt < 2; mt++)
#pragma unroll
                for (int nt = 0; nt < 8; nt++)
#pragma unroll
                    for (int q = 0; q < 4; q++) cp_[mt][nt][q] = c_[mt][nt][q];
            prevTile = g >> 2;
        }
    }
    // fold the last tile (7)
#pragma unroll
    for (int nt = 0; nt < 8; nt++) fold2(7, nt);

    // ---- quad reduce ----
#pragma unroll
    for (int si = 0; si < 4; si++) {
#pragma unroll
        for (int o = 1; o < 4; o <<= 1) {
            sum[si] += __shfl_xor_sync(0xffffffffu, sum[si], o);
            float obv = __shfl_xor_sync(0xffffffffu, bv[si], o);
            if (obv > bv[si]) bv[si] = obv;
        }
    }

    // ---- cross col-group combine ----
    float* s_sum = (float*)(smem + RED_OFF);
    float* s_bv  = (float*)(smem + RED_OFF + 512);
    __syncthreads();
    if (cg == 1 && (lane & 3) == 0) {
#pragma unroll
        for (int si = 0; si < 4; si++) { s_sum[rloc[si]] = sum[si]; s_bv[rloc[si]] = bv[si]; }
    }
    __syncthreads();
    float lossLocal = 0.f, corrLocal = 0.f;
    if (cg == 0 && (lane & 3) == 0) {
#pragma unroll
        for (int si = 0; si < 4; si++) {
            float tot = sum[si] + s_sum[rloc[si]];
            float bvv = fmaxf(bv[si], s_bv[rloc[si]]);
            lossLocal += __logf(tot) - t2d[si] * LN2;    // ln(tot)+5-gl == ln(tot)-t2d*ln2
            if (bvv < t2d[si] - M2) {
                corrLocal += 1.f;
            } else if (bvv < t2d[si] + M2) {
                int rg = rowBase + rloc[si];
                atomicOr(&g_und[rg >> 5], 1u << (rg & 31));
            }
        }
    }
#pragma unroll
    for (int o = 4; o < 32; o <<= 1) {
        lossLocal += __shfl_xor_sync(0xffffffffu, lossLocal, o);
        corrLocal += __shfl_xor_sync(0xffffffffu, corrLocal, o);
    }
    if (cg == 0 && lane == 0) {
        atomicAdd(&g_acc[0], lossLocal);
        atomicAdd(&g_acc[1], corrLocal);
    }
}

// ---------------------------------------------------------------------------
// Stage 2: exact fp32 recheck of candidate (row,col) pairs; one warp per pair.
// ---------------------------------------------------------------------------
__global__ void recheck_kernel(const float* __restrict__ emb,
                               const float* __restrict__ wp,
                               const float* __restrict__ bp)
{
    unsigned int n = g_ncand;
    if (n > CAND_CAP) n = CAND_CAP;
    const float wS = wp[0], bS = bp[0];
    int lane = threadIdx.x & 31;
    int warpG = (blockIdx.x * blockDim.x + threadIdx.x) >> 5;
    int nW = (gridDim.x * blockDim.x) >> 5;
    for (unsigned int i = warpG; i < n; i += nW) {
        unsigned int pc = g_cand[i];
        int r = pc >> 10, c = pc & 1023;
        const float* e  = emb + (size_t)r * E_DIM;
        const float* bn = g_Bn + (size_t)c * E_DIM;
        float d = 0.f;
#pragma unroll
        for (int k = 0; k < 8; k++) d += e[lane + 32 * k] * bn[lane + 32 * k];
#pragma unroll
        for (int o = 16; o > 0; o >>= 1) d += __shfl_xor_sync(0xffffffffu, d, o);
        if (lane == 0) {
            float loff = fmaf(wS, d, bS);
            float ld   = fmaf(wS, g_diag[r], bS);
            int spk = r >> 6;
            bool beat = (loff > ld) || (loff == ld && c < spk);
            if (beat) atomicOr(&g_beaten[r >> 5], 1u << (r & 31));
        }
    }
}

// ---------------------------------------------------------------------------
__global__ void finalize_kernel(float* __restrict__ out) {
    __shared__ float red[8];
    int t = threadIdx.x;
    float cnt = 0.f;
    for (int w = t; w < SU / 32; w += 256)
        cnt += (float)__popc(g_und[w] & ~g_beaten[w]);
#pragma unroll
    for (int o = 16; o > 0; o >>= 1) cnt += __shfl_xor_sync(0xffffffffu, cnt, o);
    if ((t & 31) == 0) red[t >> 5] = cnt;
    __syncthreads();
    if (t == 0) {
        float tot = 0.f;
#pragma unroll
        for (int i = 0; i < 8; i++) tot += red[i];
        out[0] = g_acc[0] * (1.f / (float)SU);
        out[1] = (g_acc[1] + tot) * (1.f / (float)SU);
    }
}

extern "C" void kernel_launch(void* const* d_in, const int* in_sizes, int n_in,
                              void* d_out, int out_size) {
    const float* emb = (const float*)d_in[0];
    const float* wp  = (const float*)d_in[1];
    const float* bp  = (const float*)d_in[2];
    float* out = (float*)d_out;

    cudaFuncSetAttribute(ge2e_main_kernel,
                         cudaFuncAttributeMaxDynamicSharedMemorySize, SMEM_TOTAL);

    zero_kernel<<<1, 256>>>();
    centroid_kernel<<<S_SPK, 256>>>(emb);
    ge2e_main_kernel<<<SU / 128, 256, SMEM_TOTAL>>>(wp, bp);
    recheck_kernel<<<2048, 128>>>(emb, wp, bp);
    finalize_kernel<<<1, 256>>>(out);
}

// round 6
// speedup vs baseline: 5.0063x; 2.0756x over previous
#include <cuda_runtime.h>
#include <cuda_bf16.h>
#include <math.h>
#include <stdint.h>

#define S_SPK 1024
#define U_UTT 64
#define E_DIM 256
#define SU (S_SPK * U_UTT)
#define LOG2E 1.4426950408889634f
#define LN2 0.6931471805599453f
#define BAND 0.02f          // row-verdict margin in log2-logit units (~14 sigma of bf16 noise)

// ---------------- scratch ----------------
__device__ __nv_bfloat16 g_Ab[(size_t)SU * E_DIM];   // embeds bf16
__device__ __nv_bfloat16 g_Bb[S_SPK * E_DIM];        // normalized centroids bf16
__device__ float g_Bn[S_SPK * E_DIM];                // fp32 normalized centroids (recheck)
__device__ float g_diag[SU];
__device__ float g_acc[2];
__device__ unsigned int g_und[SU / 32];

// ---------------- helpers ----------------
__device__ __forceinline__ uint32_t smem_u32(const void* p) {
    uint32_t a;
    asm("{ .reg .u64 t; cvta.to.shared.u64 t, %1; cvt.u32.u64 %0, t; }" : "=r"(a) : "l"(p));
    return a;
}
__device__ __forceinline__ void cp16(uint32_t dst, const void* src) {
    asm volatile("cp.async.cg.shared.global [%0], [%1], 16;" :: "r"(dst), "l"(src));
}
#define CP_COMMIT() asm volatile("cp.async.commit_group;" ::: "memory")
#define CP_WAIT2()  asm volatile("cp.async.wait_group 2;" ::: "memory")

__device__ __forceinline__ void ldsm4(uint32_t* r, uint32_t addr) {
    asm volatile("ldmatrix.sync.aligned.m8n8.x4.shared.b16 {%0,%1,%2,%3}, [%4];"
                 : "=r"(r[0]), "=r"(r[1]), "=r"(r[2]), "=r"(r[3]) : "r"(addr));
}
__device__ __forceinline__ void mma16816(float* c, const uint32_t* a, uint32_t b0, uint32_t b1) {
    asm volatile("mma.sync.aligned.m16n8k16.row.col.f32.bf16.bf16.f32 "
                 "{%0,%1,%2,%3}, {%4,%5,%6,%7}, {%8,%9}, {%0,%1,%2,%3};"
                 : "+f"(c[0]), "+f"(c[1]), "+f"(c[2]), "+f"(c[3])
                 : "r"(a[0]), "r"(a[1]), "r"(a[2]), "r"(a[3]), "r"(b0), "r"(b1));
}

// ---------------------------------------------------------------------------
__global__ void zero_kernel() {
    int t = threadIdx.x;
    if (t == 0) { g_acc[0] = 0.f; g_acc[1] = 0.f; }
    for (int w = t; w < SU / 32; w += 256) g_und[w] = 0;
}

// ---------------------------------------------------------------------------
// Kernel 1: speaker sums -> normalized dirs (fp32 + bf16), diag cosines,
//           embed bf16 conversion.
// ---------------------------------------------------------------------------
__global__ void centroid_kernel(const float* __restrict__ emb) {
    int j = blockIdx.x;
    int t = threadIdx.x;  // E column
    const float* base = emb + (size_t)j * U_UTT * E_DIM;

    float sum = 0.f;
#pragma unroll
    for (int u = 0; u < U_UTT; u++) {
        float x = base[u * E_DIM + t];
        sum += x;
        g_Ab[((size_t)j * U_UTT + u) * E_DIM + t] = __float2bfloat16_rn(x);
    }

    __shared__ float sum_sh[E_DIM];
    __shared__ float red[8];
    __shared__ float ssq_sh;
    sum_sh[t] = sum;

    float v = sum * sum;
#pragma unroll
    for (int o = 16; o > 0; o >>= 1) v += __shfl_xor_sync(0xffffffffu, v, o);
    if ((t & 31) == 0) red[t >> 5] = v;
    __syncthreads();
    if (t == 0) {
        float tot = 0.f;
#pragma unroll
        for (int i = 0; i < 8; i++) tot += red[i];
        ssq_sh = tot;
    }
    __syncthreads();
    float ssq = ssq_sh;
    float bn = sum_sh[t] * rsqrtf(ssq);
    g_Bn[(size_t)j * E_DIM + t] = bn;
    g_Bb[(size_t)j * E_DIM + t] = __float2bfloat16_rn(bn);

    int warp = t >> 5, lane = t & 31;
    for (int u = warp; u < U_UTT; u += 8) {
        const float* row = base + u * E_DIM;
        float d = 0.f, n2 = 0.f;
#pragma unroll
        for (int i = 0; i < 8; i++) {
            float x = row[lane + 32 * i];
            d  += x * sum_sh[lane + 32 * i];
            n2 += x * x;
        }
#pragma unroll
        for (int o = 16; o > 0; o >>= 1) {
            d  += __shfl_xor_sync(0xffffffffu, d,  o);
            n2 += __shfl_xor_sync(0xffffffffu, n2, o);
        }
        if (lane == 0) {
            float denom = ssq - 2.f * d + n2;
            g_diag[j * U_UTT + u] = (d - n2) * rsqrtf(denom);
        }
    }
}

// ---------------------------------------------------------------------------
// Main kernel: single-term bf16 GEMM, 128 rows x 1024 cols, K=256, fused
// softmax-sum + row-level margin verdict. 2 CTAs/SM.
// SMEM: A 64K | B ring 3x16K | red 1K  = ~113KB
// ---------------------------------------------------------------------------
#define AB_OFF 0
#define BB_OFF 65536
#define RED_OFF (BB_OFF + 3 * 16384)
#define SMEM_TOTAL (RED_OFF + 1024)

__global__ __launch_bounds__(256, 2)
void ge2e_main_kernel(const float* __restrict__ wp, const float* __restrict__ bp)
{
    extern __shared__ char smem[];
    const uint32_t sb = smem_u32(smem);
    const int tid = threadIdx.x;
    const int lane = tid & 31, wid = tid >> 5;
    const int wr = wid >> 1;          // row-group 0..3
    const int cg = wid & 1;           // col-group 0..1
    const int rowBase = blockIdx.x * 128;

    const float wS = wp[0], bS = bp[0];
    const float w2 = wS * LOG2E, b2 = (bS - 5.f) * LOG2E;

    // ---- prologue: A + B chunks 0..2 ----
#pragma unroll
    for (int k = 0; k < 16; k++) {
        int i = tid + k * 256;
        int row = i >> 5, c = i & 31;
        cp16(sb + AB_OFF + row * 512 + ((c ^ (row & 7)) << 4),
             g_Ab + (size_t)(rowBase + row) * E_DIM + c * 8);
    }
#pragma unroll
    for (int g0 = 0; g0 < 3; g0++) {
#pragma unroll
        for (int it = 0; it < 4; it++) {
            int idx = tid + it * 256;
            int row = idx >> 3, c = idx & 7;
            cp16(sb + BB_OFF + g0 * 16384 + row * 128 + ((c ^ (row & 7)) << 4),
                 g_Bb + (size_t)row * E_DIM + g0 * 64 + c * 8);
        }
        CP_COMMIT();
    }

    // ---- per-thread row state ----
    float sum[4] = {0.f, 0.f, 0.f, 0.f};
    float bv[4], t2d[4];
    int spk[4], rloc[4];
#pragma unroll
    for (int mt = 0; mt < 2; mt++)
#pragma unroll
        for (int rb = 0; rb < 2; rb++) {
            int si = mt * 2 + rb;
            int r = wr * 32 + mt * 16 + rb * 8 + (lane >> 2);
            rloc[si] = r;
            int rg = rowBase + r;
            spk[si] = rg >> 6;
            t2d[si] = fmaf(w2, g_diag[rg], b2);
            bv[si] = -1e30f;
        }

    const int sA = lane & 7;
    const int hA = lane >> 4;
    const uint32_t aRow0 = sb + AB_OFF + (uint32_t)(wr * 32 + (lane & 15)) * 512;
    const int bRow = cg * 64 + (lane & 7) + ((lane >> 4) & 1) * 8;
    const int hB = (lane >> 3) & 1;

    float c_[2][8][4];

    for (int g = 0; g < 32; g++) {               // chunk: tile = g>>2, k64 = g&3
        if ((g & 3) == 0) {
#pragma unroll
            for (int mt = 0; mt < 2; mt++)
#pragma unroll
                for (int nt = 0; nt < 8; nt++)
#pragma unroll
                    for (int q = 0; q < 4; q++) c_[mt][nt][q] = 0.f;
        }

        CP_WAIT2();
        __syncthreads();
        const uint32_t Bb = sb + BB_OFF + (uint32_t)(g % 3) * 16384;

#pragma unroll
        for (int kc = 0; kc < 4; kc++) {
            const int kg = (g & 3) * 4 + kc;
            uint32_t a[2][4];
#pragma unroll
            for (int mt = 0; mt < 2; mt++)
                ldsm4(a[mt], aRow0 + (uint32_t)(mt * 16) * 512 +
                             (uint32_t)(((2 * kg + hA) ^ sA) << 4));
            uint32_t b[4][4];
#pragma unroll
            for (int np = 0; np < 4; np++)
                ldsm4(b[np], Bb + (uint32_t)(bRow + np * 16) * 128 +
                             (uint32_t)(((2 * kc + hB) ^ sA) << 4));
#pragma unroll
            for (int mt = 0; mt < 2; mt++)
#pragma unroll
                for (int nt = 0; nt < 8; nt++)
                    mma16816(c_[mt][nt], a[mt], b[nt >> 1][(nt & 1) * 2],
                             b[nt >> 1][(nt & 1) * 2 + 1]);
        }
        __syncthreads();                          // slot free before overwrite

        if (g + 3 < 32) {
            int gn = g + 3;
            int tileN = gn >> 2, k64 = gn & 3, slot = gn % 3;
#pragma unroll
            for (int it = 0; it < 4; it++) {
                int idx = tid + it * 256;
                int row = idx >> 3, c = idx & 7;
                cp16(sb + BB_OFF + slot * 16384 + row * 128 + ((c ^ (row & 7)) << 4),
                     g_Bb + (size_t)(tileN * 128 + row) * E_DIM + k64 * 64 + c * 8);
            }
        }
        CP_COMMIT();

        if ((g & 3) == 3) {
            const int ct = g >> 2;
#pragma unroll
            for (int mt = 0; mt < 2; mt++)
#pragma unroll
                for (int nt = 0; nt < 8; nt++) {
                    int c0 = ct * 128 + cg * 64 + nt * 8 + 2 * (lane & 3);
#pragma unroll
                    for (int rb = 0; rb < 2; rb++) {
                        int si = mt * 2 + rb;
#pragma unroll
                        for (int q = 0; q < 2; q++) {
                            int cc = c0 + q;
                            float raw = fmaf(w2, c_[mt][nt][rb * 2 + q], b2);
                            float ls;
                            if (cc == spk[si]) {
                                ls = t2d[si];          // exact diag, excluded from bv
                            } else {
                                ls = raw;
                                if (raw > bv[si]) bv[si] = raw;
                            }
                            float e;
                            asm("ex2.approx.ftz.f32 %0, %1;" : "=f"(e) : "f"(ls));
                            sum[si] += e;
                        }
                    }
                }
        }
    }

    // ---- quad reduce ----
#pragma unroll
    for (int si = 0; si < 4; si++) {
#pragma unroll
        for (int o = 1; o < 4; o <<= 1) {
            sum[si] += __shfl_xor_sync(0xffffffffu, sum[si], o);
            float obv = __shfl_xor_sync(0xffffffffu, bv[si], o);
            if (obv > bv[si]) bv[si] = obv;
        }
    }

    // ---- cross col-group combine ----
    float* s_sum = (float*)(smem + RED_OFF);
    float* s_bv  = (float*)(smem + RED_OFF + 512);
    __syncthreads();
    if (cg == 1 && (lane & 3) == 0) {
#pragma unroll
        for (int si = 0; si < 4; si++) { s_sum[rloc[si]] = sum[si]; s_bv[rloc[si]] = bv[si]; }
    }
    __syncthreads();
    float lossLocal = 0.f, corrLocal = 0.f;
    if (cg == 0 && (lane & 3) == 0) {
#pragma unroll
        for (int si = 0; si < 4; si++) {
            float tot = sum[si] + s_sum[rloc[si]];
            float bvv = fmaxf(bv[si], s_bv[rloc[si]]);
            lossLocal += __logf(tot) - t2d[si] * LN2;
            if (bvv < t2d[si] - BAND) {
                corrLocal += 1.f;                 // definitely correct
            } else if (bvv < t2d[si] + BAND) {    // undecided -> exact row recheck
                int rg = rowBase + rloc[si];
                atomicOr(&g_und[rg >> 5], 1u << (rg & 31));
            }                                     // else definitely incorrect
        }
    }
#pragma unroll
    for (int o = 4; o < 32; o <<= 1) {
        lossLocal += __shfl_xor_sync(0xffffffffu, lossLocal, o);
        corrLocal += __shfl_xor_sync(0xffffffffu, corrLocal, o);
    }
    if (cg == 0 && lane == 0) {
        atomicAdd(&g_acc[0], lossLocal);
        atomicAdd(&g_acc[1], corrLocal);
    }
}

// ---------------------------------------------------------------------------
// Stage 2: exact fp32 verdict for undecided rows. 2048 blocks x 128 thr;
// block b scans rows [32b, 32b+32); for each flagged row computes all 1024
// cosines in fp32 and adds 1 to the correct-count if the diag wins.
// ---------------------------------------------------------------------------
__global__ void recheck_kernel(const float* __restrict__ emb) {
    __shared__ float e_sh[E_DIM];
    __shared__ int beaten_sh;
    int tid = threadIdx.x;
    int row0 = blockIdx.x * 32;
    for (int rr = 0; rr < 32; rr++) {
        int r = row0 + rr;
        if (!(g_und[r >> 5] & (1u << (r & 31)))) continue;

        // load embed row
        if (tid < 128) {
            e_sh[tid] = emb[(size_t)r * E_DIM + tid];
            e_sh[tid + 128] = emb[(size_t)r * E_DIM + tid + 128];
        }
        if (tid == 0) beaten_sh = 0;
        __syncthreads();

        int spk = r >> 6;
        float diag = g_diag[r];
        int beat = 0;
#pragma unroll
        for (int cc = 0; cc < 8; cc++) {
            int c = tid + cc * 128;
            if (c == spk) continue;
            const float4* bn = (const float4*)(g_Bn + (size_t)c * E_DIM);
            float d = 0.f;
#pragma unroll
            for (int k = 0; k < 64; k++) {
                float4 v = bn[k];
                const float4 e4 = *(const float4*)(e_sh + 4 * k);
                d = fmaf(v.x, e4.x, d);
                d = fmaf(v.y, e4.y, d);
                d = fmaf(v.z, e4.z, d);
                d = fmaf(v.w, e4.w, d);
            }
            if (d > diag || (d == diag && c < spk)) beat = 1;
        }
        if (beat) atomicOr(&beaten_sh, 1);
        __syncthreads();
        if (tid == 0 && !beaten_sh) atomicAdd(&g_acc[1], 1.f);
        __syncthreads();
    }
}

// ---------------------------------------------------------------------------
__global__ void finalize_kernel(float* __restrict__ out) {
    out[0] = g_acc[0] * (1.f / (float)SU);
    out[1] = g_acc[1] * (1.f / (float)SU);
}

extern "C" void kernel_launch(void* const* d_in, const int* in_sizes, int n_in,
                              void* d_out, int out_size) {
    const float* emb = (const float*)d_in[0];
    const float* wp  = (const float*)d_in[1];
    const float* bp  = (const float*)d_in[2];
    float* out = (float*)d_out;

    cudaFuncSetAttribute(ge2e_main_kernel,
                         cudaFuncAttributeMaxDynamicSharedMemorySize, SMEM_TOTAL);

    zero_kernel<<<1, 256>>>();
    centroid_kernel<<<S_SPK, 256>>>(emb);
    ge2e_main_kernel<<<SU / 128, 256, SMEM_TOTAL>>>(wp, bp);
    recheck_kernel<<<SU / 32, 128>>>(emb);
    finalize_kernel<<<1, 1>>>(out);
}

// round 7
// speedup vs baseline: 6.0298x; 1.2045x over previous
#include <cuda_runtime.h>
#include <cuda_bf16.h>
#include <math.h>
#include <stdint.h>

#define S_SPK 1024
#define U_UTT 64
#define E_DIM 256
#define SU (S_SPK * U_UTT)
#define LOG2E 1.4426950408889634f
#define LN2 0.6931471805599453f
#define BAND 0.02f          // row-verdict margin in log2-logit units (~14 sigma of bf16 noise)

// ---------------- scratch ----------------
__device__ __nv_bfloat16 g_Ab[(size_t)SU * E_DIM];   // embeds bf16
__device__ __nv_bfloat16 g_Bb[S_SPK * E_DIM];        // normalized centroids bf16
__device__ float g_Bn[S_SPK * E_DIM];                // fp32 normalized centroids (recheck)
__device__ float g_diag[SU];
__device__ float g_acc[2];
__device__ unsigned int g_nund;
__device__ unsigned int g_undlist[SU];               // each row appended at most once

// ---------------- helpers ----------------
__device__ __forceinline__ uint32_t smem_u32(const void* p) {
    uint32_t a;
    asm("{ .reg .u64 t; cvta.to.shared.u64 t, %1; cvt.u32.u64 %0, t; }" : "=r"(a) : "l"(p));
    return a;
}
__device__ __forceinline__ void cp16(uint32_t dst, const void* src) {
    asm volatile("cp.async.cg.shared.global [%0], [%1], 16;" :: "r"(dst), "l"(src));
}
#define CP_COMMIT() asm volatile("cp.async.commit_group;" ::: "memory")
#define CP_WAIT2()  asm volatile("cp.async.wait_group 2;" ::: "memory")

__device__ __forceinline__ void ldsm4(uint32_t* r, uint32_t addr) {
    asm volatile("ldmatrix.sync.aligned.m8n8.x4.shared.b16 {%0,%1,%2,%3}, [%4];"
                 : "=r"(r[0]), "=r"(r[1]), "=r"(r[2]), "=r"(r[3]) : "r"(addr));
}
__device__ __forceinline__ void mma16816(float* c, const uint32_t* a, uint32_t b0, uint32_t b1) {
    asm volatile("mma.sync.aligned.m16n8k16.row.col.f32.bf16.bf16.f32 "
                 "{%0,%1,%2,%3}, {%4,%5,%6,%7}, {%8,%9}, {%0,%1,%2,%3};"
                 : "+f"(c[0]), "+f"(c[1]), "+f"(c[2]), "+f"(c[3])
                 : "r"(a[0]), "r"(a[1]), "r"(a[2]), "r"(a[3]), "r"(b0), "r"(b1));
}

// ---------------------------------------------------------------------------
__global__ void zero_kernel() {
    g_acc[0] = 0.f; g_acc[1] = 0.f; g_nund = 0;
}

// ---------------------------------------------------------------------------
// Kernel 1: speaker sums -> normalized dirs (fp32 + bf16), diag cosines,
//           embed bf16 conversion.
// ---------------------------------------------------------------------------
__global__ void centroid_kernel(const float* __restrict__ emb) {
    int j = blockIdx.x;
    int t = threadIdx.x;  // E column
    const float* base = emb + (size_t)j * U_UTT * E_DIM;

    float sum = 0.f;
#pragma unroll
    for (int u = 0; u < U_UTT; u++) {
        float x = base[u * E_DIM + t];
        sum += x;
        g_Ab[((size_t)j * U_UTT + u) * E_DIM + t] = __float2bfloat16_rn(x);
    }

    __shared__ float sum_sh[E_DIM];
    __shared__ float red[8];
    __shared__ float ssq_sh;
    sum_sh[t] = sum;

    float v = sum * sum;
#pragma unroll
    for (int o = 16; o > 0; o >>= 1) v += __shfl_xor_sync(0xffffffffu, v, o);
    if ((t & 31) == 0) red[t >> 5] = v;
    __syncthreads();
    if (t == 0) {
        float tot = 0.f;
#pragma unroll
        for (int i = 0; i < 8; i++) tot += red[i];
        ssq_sh = tot;
    }
    __syncthreads();
    float ssq = ssq_sh;
    float bn = sum_sh[t] * rsqrtf(ssq);
    g_Bn[(size_t)j * E_DIM + t] = bn;
    g_Bb[(size_t)j * E_DIM + t] = __float2bfloat16_rn(bn);

    int warp = t >> 5, lane = t & 31;
    for (int u = warp; u < U_UTT; u += 8) {
        const float* row = base + u * E_DIM;
        float d = 0.f, n2 = 0.f;
#pragma unroll
        for (int i = 0; i < 8; i++) {
            float x = row[lane + 32 * i];
            d  += x * sum_sh[lane + 32 * i];
            n2 += x * x;
        }
#pragma unroll
        for (int o = 16; o > 0; o >>= 1) {
            d  += __shfl_xor_sync(0xffffffffu, d,  o);
            n2 += __shfl_xor_sync(0xffffffffu, n2, o);
        }
        if (lane == 0) {
            float denom = ssq - 2.f * d + n2;
            g_diag[j * U_UTT + u] = (d - n2) * rsqrtf(denom);
        }
    }
}

// ---------------------------------------------------------------------------
// Main kernel: single-term bf16 GEMM, 128 rows x 1024 cols, K=256, fused
// softmax-sum + row-level margin verdict. 2 CTAs/SM.
// SMEM: A 64K | B ring 3x16K | red 1K  = ~113KB
// ---------------------------------------------------------------------------
#define AB_OFF 0
#define BB_OFF 65536
#define RED_OFF (BB_OFF + 3 * 16384)
#define SMEM_TOTAL (RED_OFF + 1024)

__global__ __launch_bounds__(256, 2)
void ge2e_main_kernel(const float* __restrict__ wp, const float* __restrict__ bp)
{
    extern __shared__ char smem[];
    const uint32_t sb = smem_u32(smem);
    const int tid = threadIdx.x;
    const int lane = tid & 31, wid = tid >> 5;
    const int wr = wid >> 1;          // row-group 0..3
    const int cg = wid & 1;           // col-group 0..1
    const int rowBase = blockIdx.x * 128;

    const float wS = wp[0], bS = bp[0];
    const float w2 = wS * LOG2E, b2 = (bS - 5.f) * LOG2E;

    // ---- prologue: A + B chunks 0..2 ----
#pragma unroll
    for (int k = 0; k < 16; k++) {
        int i = tid + k * 256;
        int row = i >> 5, c = i & 31;
        cp16(sb + AB_OFF + row * 512 + ((c ^ (row & 7)) << 4),
             g_Ab + (size_t)(rowBase + row) * E_DIM + c * 8);
    }
#pragma unroll
    for (int g0 = 0; g0 < 3; g0++) {
#pragma unroll
        for (int it = 0; it < 4; it++) {
            int idx = tid + it * 256;
            int row = idx >> 3, c = idx & 7;
            cp16(sb + BB_OFF + g0 * 16384 + row * 128 + ((c ^ (row & 7)) << 4),
                 g_Bb + (size_t)row * E_DIM + g0 * 64 + c * 8);
        }
        CP_COMMIT();
    }

    // ---- per-thread row state ----
    float sum[4] = {0.f, 0.f, 0.f, 0.f};
    float bv[4], t2d[4];
    int spk[4], rloc[4];
#pragma unroll
    for (int mt = 0; mt < 2; mt++)
#pragma unroll
        for (int rb = 0; rb < 2; rb++) {
            int si = mt * 2 + rb;
            int r = wr * 32 + mt * 16 + rb * 8 + (lane >> 2);
            rloc[si] = r;
            int rg = rowBase + r;
            spk[si] = rg >> 6;
            t2d[si] = fmaf(w2, g_diag[rg], b2);
            bv[si] = -1e30f;
        }

    const int sA = lane & 7;
    const int hA = lane >> 4;
    const uint32_t aRow0 = sb + AB_OFF + (uint32_t)(wr * 32 + (lane & 15)) * 512;
    const int bRow = cg * 64 + (lane & 7) + ((lane >> 4) & 1) * 8;
    const int hB = (lane >> 3) & 1;

    float c_[2][8][4];

    for (int g = 0; g < 32; g++) {               // chunk: tile = g>>2, k64 = g&3
        if ((g & 3) == 0) {
#pragma unroll
            for (int mt = 0; mt < 2; mt++)
#pragma unroll
                for (int nt = 0; nt < 8; nt++)
#pragma unroll
                    for (int q = 0; q < 4; q++) c_[mt][nt][q] = 0.f;
        }

        CP_WAIT2();
        __syncthreads();
        const uint32_t Bb = sb + BB_OFF + (uint32_t)(g % 3) * 16384;

#pragma unroll
        for (int kc = 0; kc < 4; kc++) {
            const int kg = (g & 3) * 4 + kc;
            uint32_t a[2][4];
#pragma unroll
            for (int mt = 0; mt < 2; mt++)
                ldsm4(a[mt], aRow0 + (uint32_t)(mt * 16) * 512 +
                             (uint32_t)(((2 * kg + hA) ^ sA) << 4));
            uint32_t b[4][4];
#pragma unroll
            for (int np = 0; np < 4; np++)
                ldsm4(b[np], Bb + (uint32_t)(bRow + np * 16) * 128 +
                             (uint32_t)(((2 * kc + hB) ^ sA) << 4));
#pragma unroll
            for (int mt = 0; mt < 2; mt++)
#pragma unroll
                for (int nt = 0; nt < 8; nt++)
                    mma16816(c_[mt][nt], a[mt], b[nt >> 1][(nt & 1) * 2],
                             b[nt >> 1][(nt & 1) * 2 + 1]);
        }
        __syncthreads();                          // slot free before overwrite

        if (g + 3 < 32) {
            int gn = g + 3;
            int tileN = gn >> 2, k64 = gn & 3, slot = gn % 3;
#pragma unroll
            for (int it = 0; it < 4; it++) {
                int idx = tid + it * 256;
                int row = idx >> 3, c = idx & 7;
                cp16(sb + BB_OFF + slot * 16384 + row * 128 + ((c ^ (row & 7)) << 4),
                     g_Bb + (size_t)(tileN * 128 + row) * E_DIM + k64 * 64 + c * 8);
            }
        }
        CP_COMMIT();

        if ((g & 3) == 3) {
            const int ct = g >> 2;
#pragma unroll
            for (int mt = 0; mt < 2; mt++)
#pragma unroll
                for (int nt = 0; nt < 8; nt++) {
                    int c0 = ct * 128 + cg * 64 + nt * 8 + 2 * (lane & 3);
#pragma unroll
                    for (int rb = 0; rb < 2; rb++) {
                        int si = mt * 2 + rb;
#pragma unroll
                        for (int q = 0; q < 2; q++) {
                            int cc = c0 + q;
                            float raw = fmaf(w2, c_[mt][nt][rb * 2 + q], b2);
                            float ls;
                            if (cc == spk[si]) {
                                ls = t2d[si];          // exact diag, excluded from bv
                            } else {
                                ls = raw;
                                if (raw > bv[si]) bv[si] = raw;
                            }
                            float e;
                            asm("ex2.approx.ftz.f32 %0, %1;" : "=f"(e) : "f"(ls));
                            sum[si] += e;
                        }
                    }
                }
        }
    }

    // ---- quad reduce ----
#pragma unroll
    for (int si = 0; si < 4; si++) {
#pragma unroll
        for (int o = 1; o < 4; o <<= 1) {
            sum[si] += __shfl_xor_sync(0xffffffffu, sum[si], o);
            float obv = __shfl_xor_sync(0xffffffffu, bv[si], o);
            if (obv > bv[si]) bv[si] = obv;
        }
    }

    // ---- cross col-group combine ----
    float* s_sum = (float*)(smem + RED_OFF);
    float* s_bv  = (float*)(smem + RED_OFF + 512);
    __syncthreads();
    if (cg == 1 && (lane & 3) == 0) {
#pragma unroll
        for (int si = 0; si < 4; si++) { s_sum[rloc[si]] = sum[si]; s_bv[rloc[si]] = bv[si]; }
    }
    __syncthreads();
    float lossLocal = 0.f, corrLocal = 0.f;
    if (cg == 0 && (lane & 3) == 0) {
#pragma unroll
        for (int si = 0; si < 4; si++) {
            float tot = sum[si] + s_sum[rloc[si]];
            float bvv = fmaxf(bv[si], s_bv[rloc[si]]);
            lossLocal += __logf(tot) - t2d[si] * LN2;
            if (bvv < t2d[si] - BAND) {
                corrLocal += 1.f;                 // definitely correct
            } else if (bvv < t2d[si] + BAND) {    // undecided -> append to worklist
                unsigned int idx = atomicAdd(&g_nund, 1u);
                g_undlist[idx] = (unsigned)(rowBase + rloc[si]);
            }                                     // else definitely incorrect
        }
    }
#pragma unroll
    for (int o = 4; o < 32; o <<= 1) {
        lossLocal += __shfl_xor_sync(0xffffffffu, lossLocal, o);
        corrLocal += __shfl_xor_sync(0xffffffffu, corrLocal, o);
    }
    if (cg == 0 && lane == 0) {
        atomicAdd(&g_acc[0], lossLocal);
        atomicAdd(&g_acc[1], corrLocal);
    }
}

// ---------------------------------------------------------------------------
// Stage 2: exact fp32 verdict, ONE BLOCK PER UNDECIDED ROW (grid-stride over
// the compacted list). 256 threads, 4 cols/thread, 2 partial accumulators.
// ---------------------------------------------------------------------------
__global__ void recheck_kernel(const float* __restrict__ emb) {
    __shared__ float e_sh[E_DIM];
    __shared__ int beaten_sh;
    int tid = threadIdx.x;
    unsigned int n = g_nund;
    for (unsigned int i = blockIdx.x; i < n; i += gridDim.x) {
        int r = g_undlist[i];

        if (tid < 128) {
            e_sh[tid] = emb[(size_t)r * E_DIM + tid];
            e_sh[tid + 128] = emb[(size_t)r * E_DIM + tid + 128];
        }
        if (tid == 0) beaten_sh = 0;
        __syncthreads();

        int spk = r >> 6;
        float diag = g_diag[r];
        int beat = 0;
#pragma unroll
        for (int cc = 0; cc < 4; cc++) {
            int c = tid + cc * 256;
            const float4* bn = (const float4*)(g_Bn + (size_t)c * E_DIM);
            float d0 = 0.f, d1 = 0.f;
#pragma unroll
            for (int k = 0; k < 32; k++) {
                float4 v0 = bn[2 * k], v1 = bn[2 * k + 1];
                const float4 e0 = *(const float4*)(e_sh + 8 * k);
                const float4 e1 = *(const float4*)(e_sh + 8 * k + 4);
                d0 = fmaf(v0.x, e0.x, d0); d0 = fmaf(v0.y, e0.y, d0);
                d0 = fmaf(v0.z, e0.z, d0); d0 = fmaf(v0.w, e0.w, d0);
                d1 = fmaf(v1.x, e1.x, d1); d1 = fmaf(v1.y, e1.y, d1);
                d1 = fmaf(v1.z, e1.z, d1); d1 = fmaf(v1.w, e1.w, d1);
            }
            float d = d0 + d1;
            if (c != spk && (d > diag || (d == diag && c < spk))) beat = 1;
        }
        if (beat) atomicOr(&beaten_sh, 1);
        __syncthreads();
        if (tid == 0 && !beaten_sh) atomicAdd(&g_acc[1], 1.f);
        __syncthreads();
    }
}

// ---------------------------------------------------------------------------
__global__ void finalize_kernel(float* __restrict__ out) {
    out[0] = g_acc[0] * (1.f / (float)SU);
    out[1] = g_acc[1] * (1.f / (float)SU);
}

extern "C" void kernel_launch(void* const* d_in, const int* in_sizes, int n_in,
                              void* d_out, int out_size) {
    const float* emb = (const float*)d_in[0];
    const float* wp  = (const float*)d_in[1];
    const float* bp  = (const float*)d_in[2];
    float* out = (float*)d_out;

    cudaFuncSetAttribute(ge2e_main_kernel,
                         cudaFuncAttributeMaxDynamicSharedMemorySize, SMEM_TOTAL);

    zero_kernel<<<1, 1>>>();
    centroid_kernel<<<S_SPK, 256>>>(emb);
    ge2e_main_kernel<<<SU / 128, 256, SMEM_TOTAL>>>(wp, bp);
    recheck_kernel<<<1024, 256>>>(emb);
    finalize_kernel<<<1, 1>>>(out);
}